// round 10
// baseline (speedup 1.0000x reference)
#include <cuda_runtime.h>

// Problem dims (fixed by the dataset)
#define T_STEPS 20
#define BATCH   512
#define DIN     4096
#define HDIM    1024
#define CDIM    100
#define MROWS   (T_STEPS * BATCH)   // 10240

// -------- scratch (static __device__ globals; no runtime allocation) --------
__device__ float g_H[(size_t)MROWS * HDIM];      // fc1 outputs [t*B+b][h]  (40 MB)
__device__ float g_mean[T_STEPS * HDIM];
__device__ float g_istd[T_STEPS * HDIM];
__device__ float g_S[BATCH * HDIM];              // spike counts
__device__ float g_W2T[HDIM * 128];              // W2 transposed, padded to 128 cols

// ============================================================================
// Kernel 1: C[10240,1024] = A[10240,4096] * W1[1024,4096]^T   (fp32, FFMA2)
// Block tile 128(M) x 64(N), BK=16, 256 threads, 4m x 8n per thread (packed
// f32x2 pairs along N). Double-buffered smem. 1280 CTAs, occupancy 3 target
// (kills the 2.16-wave tail of the previous 640-CTA config).
// Per-output accumulation order (sequential k, FFMA2 chains) is IDENTICAL to
// the R9 passing kernel -> h is bit-identical -> no new threshold flips.
// ============================================================================
__device__ __forceinline__ void sts_tile(
    float (*As)[16][128], float (*Bs)[16][64], int buf, int lk, int lm,
    const float4& ar0, const float4& ar1, const float4& br0)
{
    As[buf][lk + 0][lm] = ar0.x;  As[buf][lk + 1][lm] = ar0.y;
    As[buf][lk + 2][lm] = ar0.z;  As[buf][lk + 3][lm] = ar0.w;
    As[buf][lk + 0][lm + 64] = ar1.x;  As[buf][lk + 1][lm + 64] = ar1.y;
    As[buf][lk + 2][lm + 64] = ar1.z;  As[buf][lk + 3][lm + 64] = ar1.w;
    Bs[buf][lk + 0][lm] = br0.x;  Bs[buf][lk + 1][lm] = br0.y;
    Bs[buf][lk + 2][lm] = br0.z;  Bs[buf][lk + 3][lm] = br0.w;
}

__global__ __launch_bounds__(256, 3)
void gemm1_kernel(const float* __restrict__ A, const float* __restrict__ W1)
{
    __shared__ __align__(16) float As[2][16][128];
    __shared__ __align__(16) float Bs[2][16][64];

    const int tid = threadIdx.x;
    const int bm  = blockIdx.y;   // 0..79   (M tiles of 128)
    const int bn  = blockIdx.x;   // 0..15   (N tiles of 64)

    // ---- global->smem loader: thread loads float4 from A rows lm, lm+64 and
    // W1 row lm, k-quad lk (64B coalesced segments per tid-quad) ----
    const int lm = tid >> 2;           // 0..63
    const int lk = (tid & 3) << 2;     // 0,4,8,12

    const float* Ap0 = A  + (size_t)(bm * 128 + lm) * DIN + lk;
    const float* Ap1 = Ap0 + (size_t)64 * DIN;
    const float* Bp0 = W1 + (size_t)(bn * 64 + lm) * DIN + lk;

    // ---- compute mapping: 8 warps as 4m x 2n of 32x32 subtiles;
    // thread = 4m x 8n (four u64 n-pairs) ----
    const int warp = tid >> 5;
    const int lane = tid & 31;
    const int m0 = (warp & 3) * 32 + (lane >> 2) * 4;    // rows m0..m0+3
    const int n0 = (warp >> 2) * 32 + (lane & 3) * 8;    // cols n0..n0+7

    const unsigned bs_base =
        (unsigned)__cvta_generic_to_shared(&Bs[0][0][0]) + (unsigned)(n0 * 4);

    unsigned long long acc[4][4];
#pragma unroll
    for (int i = 0; i < 4; i++)
#pragma unroll
        for (int j = 0; j < 4; j++) acc[i][j] = 0ull;

    // prologue: tile 0
    float4 ar0 = *(const float4*)Ap0;
    float4 ar1 = *(const float4*)Ap1;
    float4 br0 = *(const float4*)Bp0;
    sts_tile(As, Bs, 0, lk, lm, ar0, ar1, br0);
    __syncthreads();

    const int KT = DIN / 16;   // 256
    int buf = 0;
    for (int kt = 0; kt < KT; kt++) {
        if (kt + 1 < KT) {
            Ap0 += 16; Ap1 += 16; Bp0 += 16;
            ar0 = *(const float4*)Ap0;
            ar1 = *(const float4*)Ap1;
            br0 = *(const float4*)Bp0;
        }

        const float* Asb = &As[buf][0][0];
        const unsigned bbuf = bs_base + (unsigned)(buf * 16 * 64 * 4);
#pragma unroll
        for (int k = 0; k < 16; k++) {
            const float4 a0 = *(const float4*)(Asb + k * 128 + m0);
            unsigned long long bp0, bp1, bp2, bp3;
            const unsigned addr = bbuf + (unsigned)(k * 256);
            asm("ld.shared.v2.b64 {%0, %1}, [%2];"
                : "=l"(bp0), "=l"(bp1) : "r"(addr));
            asm("ld.shared.v2.b64 {%0, %1}, [%2];"
                : "=l"(bp2), "=l"(bp3) : "r"(addr + 16));

            const float av[4] = {a0.x, a0.y, a0.z, a0.w};
#pragma unroll
            for (int i = 0; i < 4; i++) {
                unsigned long long ad;
                asm("mov.b64 %0, {%1, %1};"
                    : "=l"(ad) : "r"(__float_as_uint(av[i])));
                asm("fma.rn.f32x2 %0, %1, %2, %0;" : "+l"(acc[i][0]) : "l"(ad), "l"(bp0));
                asm("fma.rn.f32x2 %0, %1, %2, %0;" : "+l"(acc[i][1]) : "l"(ad), "l"(bp1));
                asm("fma.rn.f32x2 %0, %1, %2, %0;" : "+l"(acc[i][2]) : "l"(ad), "l"(bp2));
                asm("fma.rn.f32x2 %0, %1, %2, %0;" : "+l"(acc[i][3]) : "l"(ad), "l"(bp3));
            }
        }

        if (kt + 1 < KT) {
            sts_tile(As, Bs, buf ^ 1, lk, lm, ar0, ar1, br0);
        }
        __syncthreads();
        buf ^= 1;
    }

    // epilogue: two 16B stores per row (n0 is 32B-aligned in floats)
#pragma unroll
    for (int i = 0; i < 4; i++) {
        float* r = g_H + (size_t)(bm * 128 + m0 + i) * HDIM + bn * 64 + n0;
        ulonglong2 v0; v0.x = acc[i][0]; v0.y = acc[i][1];
        ulonglong2 v1; v1.x = acc[i][2]; v1.y = acc[i][3];
        *(ulonglong2*)(r)     = v0;
        *(ulonglong2*)(r + 4) = v1;
    }
}

// ============================================================================
// Kernel 2: batch-norm stats per (t, j): mean & inv-std over B=512
// grid (4, 20), 128 threads; each thread owns 2 adjacent columns (float2).
// (Unchanged from the passing run — summation order preserved; the heaviside
// threshold makes stats numerics flip-sensitive.)
// ============================================================================
__global__ void bn_stats_kernel()
{
    const int t  = blockIdx.y;
    const int j2 = blockIdx.x * 128 + threadIdx.x;   // 0..511 (column pair)
    const float2* col = (const float2*)(g_H + (size_t)t * BATCH * HDIM) + j2;

    float s0 = 0.f, s1 = 0.f, q0 = 0.f, q1 = 0.f;
#pragma unroll 8
    for (int b = 0; b < BATCH; b++) {
        const float2 v = col[b * (HDIM / 2)];
        s0 += v.x;  q0 += v.x * v.x;
        s1 += v.y;  q1 += v.y * v.y;
    }
    const float inv = 1.0f / (float)BATCH;
    const float m0 = s0 * inv, m1 = s1 * inv;
    const int j = j2 * 2;
    g_mean[t * HDIM + j]     = m0;
    g_mean[t * HDIM + j + 1] = m1;
    g_istd[t * HDIM + j]     = rsqrtf(q0 * inv - m0 * m0 + 1e-4f);
    g_istd[t * HDIM + j + 1] = rsqrtf(q1 * inv - m1 * m1 + 1e-4f);
}

// ============================================================================
// Kernel 3: LIF recurrence -> spike counts S[b,j]   (unchanged)
// ============================================================================
__global__ void recurrence_kernel(const float* __restrict__ gamma)
{
    const int idx = blockIdx.x * 256 + threadIdx.x;   // b*1024 + j
    const int j = idx & (HDIM - 1);

    float mem = 0.f;
    float cnt = 0.f;
#pragma unroll
    for (int t = 0; t < T_STEPS; t++) {
        const float h  = g_H[(size_t)t * (BATCH * HDIM) + idx];
        const float hn = gamma[t * HDIM + j] * (h - g_mean[t * HDIM + j]) *
                         g_istd[t * HDIM + j];
        mem = 0.95f * mem + hn;
        if (mem > 1.0f) { cnt += 1.0f; mem -= 1.0f; }
    }
    g_S[idx] = cnt;
}

// ============================================================================
// Kernel 4a: transpose W2 [100,1024] -> W2T [1024,128]   (unchanged)
// ============================================================================
__global__ void transposeW2_kernel(const float* __restrict__ W2)
{
    const int idx = blockIdx.x * 256 + threadIdx.x;   // 0..131071
    const int k = idx >> 7;
    const int c = idx & 127;
    g_W2T[idx] = (c < CDIM) ? W2[c * HDIM + k] : 0.0f;
}

// ============================================================================
// Kernel 4b: out[b,c] = (1/T) * sum_k S[b,k] * W2T[k,c]   (unchanged)
// ============================================================================
__global__ void out_gemm_kernel(float* __restrict__ out)
{
    __shared__ float sS[8][HDIM];
    const int bb  = blockIdx.x;       // 0..63
    const int tid = threadIdx.x;

    for (int i = tid; i < 8 * HDIM; i += 256) {
        const int r = i >> 10, c = i & (HDIM - 1);
        sS[r][c] = g_S[(bb * 8 + r) * HDIM + c];
    }
    __syncthreads();

    const int br = tid >> 5;   // 0..7
    const int cq = tid & 31;   // 0..31 (25 active -> 100 cols)

    float4 acc = make_float4(0.f, 0.f, 0.f, 0.f);
#pragma unroll 8
    for (int k = 0; k < HDIM; k++) {
        const float  s = sS[br][k];                                 // broadcast
        const float4 w = *(const float4*)&g_W2T[k * 128 + cq * 4];  // coalesced
        acc.x += s * w.x;  acc.y += s * w.y;
        acc.z += s * w.z;  acc.w += s * w.w;
    }
    if (cq < 25) {
        const float sc = 1.0f / (float)T_STEPS;
        float4 o = make_float4(acc.x * sc, acc.y * sc, acc.z * sc, acc.w * sc);
        *(float4*)&out[(bb * 8 + br) * CDIM + cq * 4] = o;
    }
}

// ============================================================================
// launch
// ============================================================================
extern "C" void kernel_launch(void* const* d_in, const int* in_sizes, int n_in,
                              void* d_out, int out_size)
{
    const float* z     = (const float*)d_in[0];   // [20,512,4096]
    const float* W1    = (const float*)d_in[1];   // [1024,4096]
    const float* gamma = (const float*)d_in[2];   // [20,1024]
    const float* W2    = (const float*)d_in[3];   // [100,1024]
    float* out = (float*)d_out;                   // [512,100]

    gemm1_kernel<<<dim3(16, 80), 256>>>(z, W1);
    bn_stats_kernel<<<dim3(4, 20), 128>>>();
    recurrence_kernel<<<(BATCH * HDIM) / 256, 256>>>(gamma);
    transposeW2_kernel<<<(HDIM * 128) / 256, 256>>>(W2);
    out_gemm_kernel<<<BATCH / 8, 256>>>(out);
}

// round 11
// speedup vs baseline: 1.2975x; 1.2975x over previous
#include <cuda_runtime.h>

// Problem dims (fixed by the dataset)
#define T_STEPS 20
#define BATCH   512
#define DIN     4096
#define HDIM    1024
#define CDIM    100
#define MROWS   (T_STEPS * BATCH)   // 10240
#define KSPLIT  4
#define KCHUNK  (DIN / KSPLIT)      // 1024
#define HELEMS  ((size_t)MROWS * HDIM)   // 10,485,760

// -------- scratch (static __device__ globals; no runtime allocation) --------
__device__ float g_Hp[KSPLIT * HELEMS];          // split-K partials (160 MB)
__device__ float g_H[HELEMS];                    // merged fc1 outputs (40 MB)
__device__ float g_mean[T_STEPS * HDIM];
__device__ float g_istd[T_STEPS * HDIM];
__device__ float g_S[BATCH * HDIM];              // spike counts
__device__ float g_W2T[HDIM * 128];              // W2 transposed, padded to 128 cols

// ============================================================================
// Kernel 1: split-K partials of C[10240,1024] = A * W1^T   (fp32, FFMA2)
// Tile 128x128, BK=16, 256 threads, 8x8 per thread — IDENTICAL inner loop to
// the R9 passing kernel (91% in-wave FFMA2 efficiency). blockIdx.z selects a
// K=1024 chunk; grid 2560 CTAs @ occ 2 -> 8.65 waves -> 96% wave utilization
// (R9: 2.16 -> 3 waves, 72%).
// ============================================================================
__device__ __forceinline__ void sts_tile(
    float (*As)[16][128], float (*Bs)[16][128], int buf, int lk, int lm,
    const float4& ar0, const float4& ar1, const float4& br0, const float4& br1)
{
    As[buf][lk + 0][lm] = ar0.x;  As[buf][lk + 1][lm] = ar0.y;
    As[buf][lk + 2][lm] = ar0.z;  As[buf][lk + 3][lm] = ar0.w;
    As[buf][lk + 0][lm + 64] = ar1.x;  As[buf][lk + 1][lm + 64] = ar1.y;
    As[buf][lk + 2][lm + 64] = ar1.z;  As[buf][lk + 3][lm + 64] = ar1.w;
    Bs[buf][lk + 0][lm] = br0.x;  Bs[buf][lk + 1][lm] = br0.y;
    Bs[buf][lk + 2][lm] = br0.z;  Bs[buf][lk + 3][lm] = br0.w;
    Bs[buf][lk + 0][lm + 64] = br1.x;  Bs[buf][lk + 1][lm + 64] = br1.y;
    Bs[buf][lk + 2][lm + 64] = br1.z;  Bs[buf][lk + 3][lm + 64] = br1.w;
}

__global__ __launch_bounds__(256, 2)
void gemm1_kernel(const float* __restrict__ A, const float* __restrict__ W1)
{
    __shared__ __align__(16) float As[2][16][128];
    __shared__ __align__(16) float Bs[2][16][128];

    const int tid = threadIdx.x;
    const int bm  = blockIdx.y;   // 0..79
    const int bn  = blockIdx.x;   // 0..7
    const int kc  = blockIdx.z;   // 0..3  (K chunk)

    // ---- global->smem loader mapping: thread loads one float4 from rows
    // lm and lm+64, k-quad lk (perfectly coalesced 64B segments) ----
    const int lm = tid >> 2;           // 0..63
    const int lk = (tid & 3) << 2;     // 0,4,8,12

    const float* Ap0 = A  + (size_t)(bm * 128 + lm) * DIN + kc * KCHUNK + lk;
    const float* Ap1 = Ap0 + (size_t)64 * DIN;
    const float* Bp0 = W1 + (size_t)(bn * 128 + lm) * DIN + kc * KCHUNK + lk;
    const float* Bp1 = Bp0 + (size_t)64 * DIN;

    // ---- compute mapping: warp = 32m x 64n subtile; thread = 8m x (4+4)n ----
    const int warp = tid >> 5;
    const int lane = tid & 31;
    const int m0 = (warp >> 1) * 32 + (lane >> 3) * 8;            // 8 rows m0..m0+7
    const int n0 = (warp & 1) * 64 + (lane & 7) * 4;              // cols n0..n0+3, n0+32..n0+35

    const unsigned bs_base =
        (unsigned)__cvta_generic_to_shared(&Bs[0][0][0]) + (unsigned)(n0 * 4);

    unsigned long long acc[8][4];
#pragma unroll
    for (int i = 0; i < 8; i++)
#pragma unroll
        for (int j = 0; j < 4; j++) acc[i][j] = 0ull;

    // prologue: tile 0
    float4 ar0 = *(const float4*)Ap0;
    float4 ar1 = *(const float4*)Ap1;
    float4 br0 = *(const float4*)Bp0;
    float4 br1 = *(const float4*)Bp1;
    sts_tile(As, Bs, 0, lk, lm, ar0, ar1, br0, br1);
    __syncthreads();

    const int KT = KCHUNK / 16;   // 64
    int buf = 0;
    for (int kt = 0; kt < KT; kt++) {
        if (kt + 1 < KT) {
            Ap0 += 16; Ap1 += 16; Bp0 += 16; Bp1 += 16;
            ar0 = *(const float4*)Ap0;
            ar1 = *(const float4*)Ap1;
            br0 = *(const float4*)Bp0;
            br1 = *(const float4*)Bp1;
        }

        const float* Asb = &As[buf][0][0];
        const unsigned bbuf = bs_base + (unsigned)(buf * 16 * 128 * 4);
#pragma unroll
        for (int k = 0; k < 16; k++) {
            const float4 a0 = *(const float4*)(Asb + k * 128 + m0);
            const float4 a1 = *(const float4*)(Asb + k * 128 + m0 + 4);
            unsigned long long bp0, bp1, bp2, bp3;
            const unsigned addr = bbuf + (unsigned)(k * 512);
            asm("ld.shared.v2.b64 {%0, %1}, [%2];"
                : "=l"(bp0), "=l"(bp1) : "r"(addr));
            asm("ld.shared.v2.b64 {%0, %1}, [%2];"
                : "=l"(bp2), "=l"(bp3) : "r"(addr + 128));

            const float av[8] = {a0.x, a0.y, a0.z, a0.w, a1.x, a1.y, a1.z, a1.w};
#pragma unroll
            for (int i = 0; i < 8; i++) {
                unsigned long long ad;
                asm("mov.b64 %0, {%1, %1};"
                    : "=l"(ad) : "r"(__float_as_uint(av[i])));
                asm("fma.rn.f32x2 %0, %1, %2, %0;" : "+l"(acc[i][0]) : "l"(ad), "l"(bp0));
                asm("fma.rn.f32x2 %0, %1, %2, %0;" : "+l"(acc[i][1]) : "l"(ad), "l"(bp1));
                asm("fma.rn.f32x2 %0, %1, %2, %0;" : "+l"(acc[i][2]) : "l"(ad), "l"(bp2));
                asm("fma.rn.f32x2 %0, %1, %2, %0;" : "+l"(acc[i][3]) : "l"(ad), "l"(bp3));
            }
        }

        if (kt + 1 < KT) {
            sts_tile(As, Bs, buf ^ 1, lk, lm, ar0, ar1, br0, br1);
        }
        __syncthreads();
        buf ^= 1;
    }

    // epilogue: store accumulator pairs into this chunk's partial plane
    float* Hp = g_Hp + (size_t)kc * HELEMS;
#pragma unroll
    for (int i = 0; i < 8; i++) {
        float* r = Hp + (size_t)(bm * 128 + m0 + i) * HDIM + bn * 128 + n0;
        *(unsigned long long*)(r)      = acc[i][0];
        *(unsigned long long*)(r + 2)  = acc[i][1];
        *(unsigned long long*)(r + 32) = acc[i][2];
        *(unsigned long long*)(r + 34) = acc[i][3];
    }
}

// ============================================================================
// Kernel 1b: deterministic split-K merge: g_H = ((p0+p1)+p2)+p3  (float4)
// ============================================================================
__global__ void merge_kernel()
{
    const size_t i = ((size_t)blockIdx.x * 256 + threadIdx.x) * 4;
    const float4 p0 = *(const float4*)(g_Hp + i);
    const float4 p1 = *(const float4*)(g_Hp + HELEMS + i);
    const float4 p2 = *(const float4*)(g_Hp + 2 * HELEMS + i);
    const float4 p3 = *(const float4*)(g_Hp + 3 * HELEMS + i);
    float4 s;
    s.x = ((p0.x + p1.x) + p2.x) + p3.x;
    s.y = ((p0.y + p1.y) + p2.y) + p3.y;
    s.z = ((p0.z + p1.z) + p2.z) + p3.z;
    s.w = ((p0.w + p1.w) + p2.w) + p3.w;
    *(float4*)(g_H + i) = s;
}

// ============================================================================
// Kernel 2: batch-norm stats per (t, j): mean & inv-std over B=512 (unchanged)
// ============================================================================
__global__ void bn_stats_kernel()
{
    const int t  = blockIdx.y;
    const int j2 = blockIdx.x * 128 + threadIdx.x;   // 0..511 (column pair)
    const float2* col = (const float2*)(g_H + (size_t)t * BATCH * HDIM) + j2;

    float s0 = 0.f, s1 = 0.f, q0 = 0.f, q1 = 0.f;
#pragma unroll 8
    for (int b = 0; b < BATCH; b++) {
        const float2 v = col[b * (HDIM / 2)];
        s0 += v.x;  q0 += v.x * v.x;
        s1 += v.y;  q1 += v.y * v.y;
    }
    const float inv = 1.0f / (float)BATCH;
    const float m0 = s0 * inv, m1 = s1 * inv;
    const int j = j2 * 2;
    g_mean[t * HDIM + j]     = m0;
    g_mean[t * HDIM + j + 1] = m1;
    g_istd[t * HDIM + j]     = rsqrtf(q0 * inv - m0 * m0 + 1e-4f);
    g_istd[t * HDIM + j + 1] = rsqrtf(q1 * inv - m1 * m1 + 1e-4f);
}

// ============================================================================
// Kernel 3: LIF recurrence -> spike counts S[b,j]   (unchanged)
// ============================================================================
__global__ void recurrence_kernel(const float* __restrict__ gamma)
{
    const int idx = blockIdx.x * 256 + threadIdx.x;   // b*1024 + j
    const int j = idx & (HDIM - 1);

    float mem = 0.f;
    float cnt = 0.f;
#pragma unroll
    for (int t = 0; t < T_STEPS; t++) {
        const float h  = g_H[(size_t)t * (BATCH * HDIM) + idx];
        const float hn = gamma[t * HDIM + j] * (h - g_mean[t * HDIM + j]) *
                         g_istd[t * HDIM + j];
        mem = 0.95f * mem + hn;
        if (mem > 1.0f) { cnt += 1.0f; mem -= 1.0f; }
    }
    g_S[idx] = cnt;
}

// ============================================================================
// Kernel 4a: transpose W2 [100,1024] -> W2T [1024,128]   (unchanged)
// ============================================================================
__global__ void transposeW2_kernel(const float* __restrict__ W2)
{
    const int idx = blockIdx.x * 256 + threadIdx.x;   // 0..131071
    const int k = idx >> 7;
    const int c = idx & 127;
    g_W2T[idx] = (c < CDIM) ? W2[c * HDIM + k] : 0.0f;
}

// ============================================================================
// Kernel 4b: out[b,c] = (1/T) * sum_k S[b,k] * W2T[k,c]   (unchanged)
// ============================================================================
__global__ void out_gemm_kernel(float* __restrict__ out)
{
    __shared__ float sS[8][HDIM];
    const int bb  = blockIdx.x;       // 0..63
    const int tid = threadIdx.x;

    for (int i = tid; i < 8 * HDIM; i += 256) {
        const int r = i >> 10, c = i & (HDIM - 1);
        sS[r][c] = g_S[(bb * 8 + r) * HDIM + c];
    }
    __syncthreads();

    const int br = tid >> 5;   // 0..7
    const int cq = tid & 31;   // 0..31 (25 active -> 100 cols)

    float4 acc = make_float4(0.f, 0.f, 0.f, 0.f);
#pragma unroll 8
    for (int k = 0; k < HDIM; k++) {
        const float  s = sS[br][k];                                 // broadcast
        const float4 w = *(const float4*)&g_W2T[k * 128 + cq * 4];  // coalesced
        acc.x += s * w.x;  acc.y += s * w.y;
        acc.z += s * w.z;  acc.w += s * w.w;
    }
    if (cq < 25) {
        const float sc = 1.0f / (float)T_STEPS;
        float4 o = make_float4(acc.x * sc, acc.y * sc, acc.z * sc, acc.w * sc);
        *(float4*)&out[(bb * 8 + br) * CDIM + cq * 4] = o;
    }
}

// ============================================================================
// launch
// ============================================================================
extern "C" void kernel_launch(void* const* d_in, const int* in_sizes, int n_in,
                              void* d_out, int out_size)
{
    const float* z     = (const float*)d_in[0];   // [20,512,4096]
    const float* W1    = (const float*)d_in[1];   // [1024,4096]
    const float* gamma = (const float*)d_in[2];   // [20,1024]
    const float* W2    = (const float*)d_in[3];   // [100,1024]
    float* out = (float*)d_out;                   // [512,100]

    gemm1_kernel<<<dim3(8, 80, KSPLIT), 256>>>(z, W1);
    merge_kernel<<<(unsigned)(HELEMS / 4 / 256), 256>>>();
    bn_stats_kernel<<<dim3(4, 20), 128>>>();
    recurrence_kernel<<<(BATCH * HDIM) / 256, 256>>>(gamma);
    transposeW2_kernel<<<(HDIM * 128) / 256, 256>>>(W2);
    out_gemm_kernel<<<BATCH / 8, 256>>>(out);
}

// round 12
// speedup vs baseline: 1.2979x; 1.0003x over previous
#include <cuda_runtime.h>

// Problem dims (fixed by the dataset)
#define T_STEPS 20
#define BATCH   512
#define DIN     4096
#define HDIM    1024
#define CDIM    100
#define MROWS   (T_STEPS * BATCH)   // 10240
#define KSPLIT  4
#define KCHUNK  (DIN / KSPLIT)      // 1024
#define HELEMS  ((size_t)MROWS * HDIM)   // 10,485,760

// -------- scratch (static __device__ globals; no runtime allocation) --------
__device__ float g_Hp[KSPLIT * HELEMS];          // split-K partials (160 MB)
__device__ float g_H[HELEMS];                    // merged fc1 outputs (40 MB)
__device__ float g_mean[T_STEPS * HDIM];
__device__ float g_istd[T_STEPS * HDIM];
__device__ float g_S[BATCH * HDIM];              // spike counts
__device__ float g_W2T[HDIM * 128];              // W2 transposed, padded to 128 cols

// ============================================================================
// Kernel 1: split-K partials of C[10240,1024] = A * W1^T   (fp32, FFMA2)
// Tile 128x128, BK=16, 256 threads, 8x8 per thread — IDENTICAL inner loop to
// the R9 passing kernel (91% in-wave FFMA2 efficiency). blockIdx.z selects a
// K=1024 chunk; grid 2560 CTAs @ occ 2 -> 8.65 waves -> 96% wave utilization
// (R9: 2.16 -> 3 waves, 72%).
// ============================================================================
__device__ __forceinline__ void sts_tile(
    float (*As)[16][128], float (*Bs)[16][128], int buf, int lk, int lm,
    const float4& ar0, const float4& ar1, const float4& br0, const float4& br1)
{
    As[buf][lk + 0][lm] = ar0.x;  As[buf][lk + 1][lm] = ar0.y;
    As[buf][lk + 2][lm] = ar0.z;  As[buf][lk + 3][lm] = ar0.w;
    As[buf][lk + 0][lm + 64] = ar1.x;  As[buf][lk + 1][lm + 64] = ar1.y;
    As[buf][lk + 2][lm + 64] = ar1.z;  As[buf][lk + 3][lm + 64] = ar1.w;
    Bs[buf][lk + 0][lm] = br0.x;  Bs[buf][lk + 1][lm] = br0.y;
    Bs[buf][lk + 2][lm] = br0.z;  Bs[buf][lk + 3][lm] = br0.w;
    Bs[buf][lk + 0][lm + 64] = br1.x;  Bs[buf][lk + 1][lm + 64] = br1.y;
    Bs[buf][lk + 2][lm + 64] = br1.z;  Bs[buf][lk + 3][lm + 64] = br1.w;
}

__global__ __launch_bounds__(256, 2)
void gemm1_kernel(const float* __restrict__ A, const float* __restrict__ W1)
{
    __shared__ __align__(16) float As[2][16][128];
    __shared__ __align__(16) float Bs[2][16][128];

    const int tid = threadIdx.x;
    const int bm  = blockIdx.y;   // 0..79
    const int bn  = blockIdx.x;   // 0..7
    const int kc  = blockIdx.z;   // 0..3  (K chunk)

    // ---- global->smem loader mapping: thread loads one float4 from rows
    // lm and lm+64, k-quad lk (perfectly coalesced 64B segments) ----
    const int lm = tid >> 2;           // 0..63
    const int lk = (tid & 3) << 2;     // 0,4,8,12

    const float* Ap0 = A  + (size_t)(bm * 128 + lm) * DIN + kc * KCHUNK + lk;
    const float* Ap1 = Ap0 + (size_t)64 * DIN;
    const float* Bp0 = W1 + (size_t)(bn * 128 + lm) * DIN + kc * KCHUNK + lk;
    const float* Bp1 = Bp0 + (size_t)64 * DIN;

    // ---- compute mapping: warp = 32m x 64n subtile; thread = 8m x (4+4)n ----
    const int warp = tid >> 5;
    const int lane = tid & 31;
    const int m0 = (warp >> 1) * 32 + (lane >> 3) * 8;            // 8 rows m0..m0+7
    const int n0 = (warp & 1) * 64 + (lane & 7) * 4;              // cols n0..n0+3, n0+32..n0+35

    const unsigned bs_base =
        (unsigned)__cvta_generic_to_shared(&Bs[0][0][0]) + (unsigned)(n0 * 4);

    unsigned long long acc[8][4];
#pragma unroll
    for (int i = 0; i < 8; i++)
#pragma unroll
        for (int j = 0; j < 4; j++) acc[i][j] = 0ull;

    // prologue: tile 0
    float4 ar0 = *(const float4*)Ap0;
    float4 ar1 = *(const float4*)Ap1;
    float4 br0 = *(const float4*)Bp0;
    float4 br1 = *(const float4*)Bp1;
    sts_tile(As, Bs, 0, lk, lm, ar0, ar1, br0, br1);
    __syncthreads();

    const int KT = KCHUNK / 16;   // 64
    int buf = 0;
    for (int kt = 0; kt < KT; kt++) {
        if (kt + 1 < KT) {
            Ap0 += 16; Ap1 += 16; Bp0 += 16; Bp1 += 16;
            ar0 = *(const float4*)Ap0;
            ar1 = *(const float4*)Ap1;
            br0 = *(const float4*)Bp0;
            br1 = *(const float4*)Bp1;
        }

        const float* Asb = &As[buf][0][0];
        const unsigned bbuf = bs_base + (unsigned)(buf * 16 * 128 * 4);
#pragma unroll
        for (int k = 0; k < 16; k++) {
            const float4 a0 = *(const float4*)(Asb + k * 128 + m0);
            const float4 a1 = *(const float4*)(Asb + k * 128 + m0 + 4);
            unsigned long long bp0, bp1, bp2, bp3;
            const unsigned addr = bbuf + (unsigned)(k * 512);
            asm("ld.shared.v2.b64 {%0, %1}, [%2];"
                : "=l"(bp0), "=l"(bp1) : "r"(addr));
            asm("ld.shared.v2.b64 {%0, %1}, [%2];"
                : "=l"(bp2), "=l"(bp3) : "r"(addr + 128));

            const float av[8] = {a0.x, a0.y, a0.z, a0.w, a1.x, a1.y, a1.z, a1.w};
#pragma unroll
            for (int i = 0; i < 8; i++) {
                unsigned long long ad;
                asm("mov.b64 %0, {%1, %1};"
                    : "=l"(ad) : "r"(__float_as_uint(av[i])));
                asm("fma.rn.f32x2 %0, %1, %2, %0;" : "+l"(acc[i][0]) : "l"(ad), "l"(bp0));
                asm("fma.rn.f32x2 %0, %1, %2, %0;" : "+l"(acc[i][1]) : "l"(ad), "l"(bp1));
                asm("fma.rn.f32x2 %0, %1, %2, %0;" : "+l"(acc[i][2]) : "l"(ad), "l"(bp2));
                asm("fma.rn.f32x2 %0, %1, %2, %0;" : "+l"(acc[i][3]) : "l"(ad), "l"(bp3));
            }
        }

        if (kt + 1 < KT) {
            sts_tile(As, Bs, buf ^ 1, lk, lm, ar0, ar1, br0, br1);
        }
        __syncthreads();
        buf ^= 1;
    }

    // epilogue: store accumulator pairs into this chunk's partial plane
    float* Hp = g_Hp + (size_t)kc * HELEMS;
#pragma unroll
    for (int i = 0; i < 8; i++) {
        float* r = Hp + (size_t)(bm * 128 + m0 + i) * HDIM + bn * 128 + n0;
        *(unsigned long long*)(r)      = acc[i][0];
        *(unsigned long long*)(r + 2)  = acc[i][1];
        *(unsigned long long*)(r + 32) = acc[i][2];
        *(unsigned long long*)(r + 34) = acc[i][3];
    }
}

// ============================================================================
// Kernel 1b: deterministic split-K merge: g_H = ((p0+p1)+p2)+p3  (float4)
// ============================================================================
__global__ void merge_kernel()
{
    const size_t i = ((size_t)blockIdx.x * 256 + threadIdx.x) * 4;
    const float4 p0 = *(const float4*)(g_Hp + i);
    const float4 p1 = *(const float4*)(g_Hp + HELEMS + i);
    const float4 p2 = *(const float4*)(g_Hp + 2 * HELEMS + i);
    const float4 p3 = *(const float4*)(g_Hp + 3 * HELEMS + i);
    float4 s;
    s.x = ((p0.x + p1.x) + p2.x) + p3.x;
    s.y = ((p0.y + p1.y) + p2.y) + p3.y;
    s.z = ((p0.z + p1.z) + p2.z) + p3.z;
    s.w = ((p0.w + p1.w) + p2.w) + p3.w;
    *(float4*)(g_H + i) = s;
}

// ============================================================================
// Kernel 2: batch-norm stats per (t, j): mean & inv-std over B=512 (unchanged)
// ============================================================================
__global__ void bn_stats_kernel()
{
    const int t  = blockIdx.y;
    const int j2 = blockIdx.x * 128 + threadIdx.x;   // 0..511 (column pair)
    const float2* col = (const float2*)(g_H + (size_t)t * BATCH * HDIM) + j2;

    float s0 = 0.f, s1 = 0.f, q0 = 0.f, q1 = 0.f;
#pragma unroll 8
    for (int b = 0; b < BATCH; b++) {
        const float2 v = col[b * (HDIM / 2)];
        s0 += v.x;  q0 += v.x * v.x;
        s1 += v.y;  q1 += v.y * v.y;
    }
    const float inv = 1.0f / (float)BATCH;
    const float m0 = s0 * inv, m1 = s1 * inv;
    const int j = j2 * 2;
    g_mean[t * HDIM + j]     = m0;
    g_mean[t * HDIM + j + 1] = m1;
    g_istd[t * HDIM + j]     = rsqrtf(q0 * inv - m0 * m0 + 1e-4f);
    g_istd[t * HDIM + j + 1] = rsqrtf(q1 * inv - m1 * m1 + 1e-4f);
}

// ============================================================================
// Kernel 3: LIF recurrence -> spike counts S[b,j]   (unchanged)
// ============================================================================
__global__ void recurrence_kernel(const float* __restrict__ gamma)
{
    const int idx = blockIdx.x * 256 + threadIdx.x;   // b*1024 + j
    const int j = idx & (HDIM - 1);

    float mem = 0.f;
    float cnt = 0.f;
#pragma unroll
    for (int t = 0; t < T_STEPS; t++) {
        const float h  = g_H[(size_t)t * (BATCH * HDIM) + idx];
        const float hn = gamma[t * HDIM + j] * (h - g_mean[t * HDIM + j]) *
                         g_istd[t * HDIM + j];
        mem = 0.95f * mem + hn;
        if (mem > 1.0f) { cnt += 1.0f; mem -= 1.0f; }
    }
    g_S[idx] = cnt;
}

// ============================================================================
// Kernel 4a: transpose W2 [100,1024] -> W2T [1024,128]   (unchanged)
// ============================================================================
__global__ void transposeW2_kernel(const float* __restrict__ W2)
{
    const int idx = blockIdx.x * 256 + threadIdx.x;   // 0..131071
    const int k = idx >> 7;
    const int c = idx & 127;
    g_W2T[idx] = (c < CDIM) ? W2[c * HDIM + k] : 0.0f;
}

// ============================================================================
// Kernel 4b: out[b,c] = (1/T) * sum_k S[b,k] * W2T[k,c]   (unchanged)
// ============================================================================
__global__ void out_gemm_kernel(float* __restrict__ out)
{
    __shared__ float sS[8][HDIM];
    const int bb  = blockIdx.x;       // 0..63
    const int tid = threadIdx.x;

    for (int i = tid; i < 8 * HDIM; i += 256) {
        const int r = i >> 10, c = i & (HDIM - 1);
        sS[r][c] = g_S[(bb * 8 + r) * HDIM + c];
    }
    __syncthreads();

    const int br = tid >> 5;   // 0..7
    const int cq = tid & 31;   // 0..31 (25 active -> 100 cols)

    float4 acc = make_float4(0.f, 0.f, 0.f, 0.f);
#pragma unroll 8
    for (int k = 0; k < HDIM; k++) {
        const float  s = sS[br][k];                                 // broadcast
        const float4 w = *(const float4*)&g_W2T[k * 128 + cq * 4];  // coalesced
        acc.x += s * w.x;  acc.y += s * w.y;
        acc.z += s * w.z;  acc.w += s * w.w;
    }
    if (cq < 25) {
        const float sc = 1.0f / (float)T_STEPS;
        float4 o = make_float4(acc.x * sc, acc.y * sc, acc.z * sc, acc.w * sc);
        *(float4*)&out[(bb * 8 + br) * CDIM + cq * 4] = o;
    }
}

// ============================================================================
// launch
// ============================================================================
extern "C" void kernel_launch(void* const* d_in, const int* in_sizes, int n_in,
                              void* d_out, int out_size)
{
    const float* z     = (const float*)d_in[0];   // [20,512,4096]
    const float* W1    = (const float*)d_in[1];   // [1024,4096]
    const float* gamma = (const float*)d_in[2];   // [20,1024]
    const float* W2    = (const float*)d_in[3];   // [100,1024]
    float* out = (float*)d_out;                   // [512,100]

    gemm1_kernel<<<dim3(8, 80, KSPLIT), 256>>>(z, W1);
    merge_kernel<<<(unsigned)(HELEMS / 4 / 256), 256>>>();
    bn_stats_kernel<<<dim3(4, 20), 128>>>();
    recurrence_kernel<<<(BATCH * HDIM) / 256, 256>>>(gamma);
    transposeW2_kernel<<<(HDIM * 128) / 256, 256>>>(W2);
    out_gemm_kernel<<<BATCH / 8, 256>>>(out);
}

// round 13
// speedup vs baseline: 1.4234x; 1.0967x over previous
#include <cuda_runtime.h>

// Problem dims (fixed by the dataset)
#define T_STEPS 20
#define BATCH   512
#define DIN     4096
#define HDIM    1024
#define CDIM    100
#define MROWS   (T_STEPS * BATCH)   // 10240
#define KSPLIT  4
#define KCHUNK  (DIN / KSPLIT)      // 1024
#define HELEMS  ((size_t)MROWS * HDIM)   // 10,485,760

// -------- scratch (static __device__ globals; no runtime allocation) --------
__device__ float g_Hp[KSPLIT * HELEMS];          // split-K partials (160 MB)
__device__ float g_H[HELEMS];                    // merged fc1 outputs (40 MB)
__device__ float g_mean[T_STEPS * HDIM];
__device__ float g_istd[T_STEPS * HDIM];
__device__ float g_S[BATCH * HDIM];              // spike counts
__device__ float g_W2T[HDIM * 128];              // W2 transposed, padded to 128 cols

// ============================================================================
// Kernel 1: split-K partials of C[10240,1024] = A * W1^T   (fp32, FFMA2)
// Tile 128x128, BK=16, 256 threads, 8x8 per thread. Split-K=4 (96% wave util).
// NEW vs R12: XOR bank swizzle on smem columns — col_phys = col ^ ((row&12)<<1)
// for both As and Bs, applied at store AND load. Removes the 4-way STS bank
// conflict (row stride 128 floats is bank-aligned, so lanes with equal lm and
// lk in {0,4,8,12} previously hit one bank). Arithmetic is bit-identical.
// ============================================================================
__device__ __forceinline__ void sts_tile(
    float (*As)[16][128], float (*Bs)[16][128], int buf, int lk, int lmx,
    const float4& ar0, const float4& ar1, const float4& br0, const float4& br1)
{
    // lmx = lm ^ (lk << 1): swizzled column, same mask for rows lk..lk+3
    // (since (lk+i)&12 == lk for i<4). Bit 6 (the +64) is untouched by the mask.
    As[buf][lk + 0][lmx] = ar0.x;  As[buf][lk + 1][lmx] = ar0.y;
    As[buf][lk + 2][lmx] = ar0.z;  As[buf][lk + 3][lmx] = ar0.w;
    As[buf][lk + 0][lmx + 64] = ar1.x;  As[buf][lk + 1][lmx + 64] = ar1.y;
    As[buf][lk + 2][lmx + 64] = ar1.z;  As[buf][lk + 3][lmx + 64] = ar1.w;
    Bs[buf][lk + 0][lmx] = br0.x;  Bs[buf][lk + 1][lmx] = br0.y;
    Bs[buf][lk + 2][lmx] = br0.z;  Bs[buf][lk + 3][lmx] = br0.w;
    Bs[buf][lk + 0][lmx + 64] = br1.x;  Bs[buf][lk + 1][lmx + 64] = br1.y;
    Bs[buf][lk + 2][lmx + 64] = br1.z;  Bs[buf][lk + 3][lmx + 64] = br1.w;
}

__global__ __launch_bounds__(256, 2)
void gemm1_kernel(const float* __restrict__ A, const float* __restrict__ W1)
{
    __shared__ __align__(16) float As[2][16][128];
    __shared__ __align__(16) float Bs[2][16][128];

    const int tid = threadIdx.x;
    const int bm  = blockIdx.y;   // 0..79
    const int bn  = blockIdx.x;   // 0..7
    const int kc  = blockIdx.z;   // 0..3  (K chunk)

    // ---- global->smem loader mapping (coalesced 64B segments per tid-quad) --
    const int lm = tid >> 2;           // 0..63
    const int lk = (tid & 3) << 2;     // 0,4,8,12
    const int lmx = lm ^ (lk << 1);    // swizzled smem column

    const float* Ap0 = A  + (size_t)(bm * 128 + lm) * DIN + kc * KCHUNK + lk;
    const float* Ap1 = Ap0 + (size_t)64 * DIN;
    const float* Bp0 = W1 + (size_t)(bn * 128 + lm) * DIN + kc * KCHUNK + lk;
    const float* Bp1 = Bp0 + (size_t)64 * DIN;

    // ---- compute mapping: warp = 32m x 64n subtile; thread = 8m x (4+4)n ----
    const int warp = tid >> 5;
    const int lane = tid & 31;
    const int m0 = (warp >> 1) * 32 + (lane >> 3) * 8;   // mult of 8
    const int n0 = (warp & 1) * 64 + (lane & 7) * 4;     // mult of 4

    const unsigned bs_base =
        (unsigned)__cvta_generic_to_shared(&Bs[0][0][0]);

    unsigned long long acc[8][4];
#pragma unroll
    for (int i = 0; i < 8; i++)
#pragma unroll
        for (int j = 0; j < 4; j++) acc[i][j] = 0ull;

    // prologue: tile 0
    float4 ar0 = *(const float4*)Ap0;
    float4 ar1 = *(const float4*)Ap1;
    float4 br0 = *(const float4*)Bp0;
    float4 br1 = *(const float4*)Bp1;
    sts_tile(As, Bs, 0, lk, lmx, ar0, ar1, br0, br1);
    __syncthreads();

    const int KT = KCHUNK / 16;   // 64
    int buf = 0;
    for (int kt = 0; kt < KT; kt++) {
        if (kt + 1 < KT) {
            Ap0 += 16; Ap1 += 16; Bp0 += 16; Bp1 += 16;
            ar0 = *(const float4*)Ap0;
            ar1 = *(const float4*)Ap1;
            br0 = *(const float4*)Bp0;
            br1 = *(const float4*)Bp1;
        }

        const float* Asb = &As[buf][0][0];
        const unsigned bbuf = bs_base + (unsigned)(buf * 16 * 128 * 4);
#pragma unroll
        for (int k = 0; k < 16; k++) {
            const int sw = (k & 12) << 1;                 // compile-time per k
            const float4 a0 = *(const float4*)(Asb + k * 128 + (m0 ^ sw));
            const float4 a1 = *(const float4*)(Asb + k * 128 + (m0 ^ sw) + 4);
            unsigned long long bp0, bp1, bp2, bp3;
            const unsigned addr = bbuf + (unsigned)((k * 128 + (n0 ^ sw)) * 4);
            asm("ld.shared.v2.b64 {%0, %1}, [%2];"
                : "=l"(bp0), "=l"(bp1) : "r"(addr));
            asm("ld.shared.v2.b64 {%0, %1}, [%2];"
                : "=l"(bp2), "=l"(bp3) : "r"(addr + 128));

            const float av[8] = {a0.x, a0.y, a0.z, a0.w, a1.x, a1.y, a1.z, a1.w};
#pragma unroll
            for (int i = 0; i < 8; i++) {
                unsigned long long ad;
                asm("mov.b64 %0, {%1, %1};"
                    : "=l"(ad) : "r"(__float_as_uint(av[i])));
                asm("fma.rn.f32x2 %0, %1, %2, %0;" : "+l"(acc[i][0]) : "l"(ad), "l"(bp0));
                asm("fma.rn.f32x2 %0, %1, %2, %0;" : "+l"(acc[i][1]) : "l"(ad), "l"(bp1));
                asm("fma.rn.f32x2 %0, %1, %2, %0;" : "+l"(acc[i][2]) : "l"(ad), "l"(bp2));
                asm("fma.rn.f32x2 %0, %1, %2, %0;" : "+l"(acc[i][3]) : "l"(ad), "l"(bp3));
            }
        }

        if (kt + 1 < KT) {
            sts_tile(As, Bs, buf ^ 1, lk, lmx, ar0, ar1, br0, br1);
        }
        __syncthreads();
        buf ^= 1;
    }

    // epilogue: store accumulator pairs into this chunk's partial plane
    float* Hp = g_Hp + (size_t)kc * HELEMS;
#pragma unroll
    for (int i = 0; i < 8; i++) {
        float* r = Hp + (size_t)(bm * 128 + m0 + i) * HDIM + bn * 128 + n0;
        *(unsigned long long*)(r)      = acc[i][0];
        *(unsigned long long*)(r + 2)  = acc[i][1];
        *(unsigned long long*)(r + 32) = acc[i][2];
        *(unsigned long long*)(r + 34) = acc[i][3];
    }
}

// ============================================================================
// Kernel 1b: deterministic split-K merge: g_H = ((p0+p1)+p2)+p3  (unchanged)
// ============================================================================
__global__ void merge_kernel()
{
    const size_t i = ((size_t)blockIdx.x * 256 + threadIdx.x) * 4;
    const float4 p0 = *(const float4*)(g_Hp + i);
    const float4 p1 = *(const float4*)(g_Hp + HELEMS + i);
    const float4 p2 = *(const float4*)(g_Hp + 2 * HELEMS + i);
    const float4 p3 = *(const float4*)(g_Hp + 3 * HELEMS + i);
    float4 s;
    s.x = ((p0.x + p1.x) + p2.x) + p3.x;
    s.y = ((p0.y + p1.y) + p2.y) + p3.y;
    s.z = ((p0.z + p1.z) + p2.z) + p3.z;
    s.w = ((p0.w + p1.w) + p2.w) + p3.w;
    *(float4*)(g_H + i) = s;
}

// ============================================================================
// Kernel 2: batch-norm stats per (t, j)   (unchanged)
// ============================================================================
__global__ void bn_stats_kernel()
{
    const int t  = blockIdx.y;
    const int j2 = blockIdx.x * 128 + threadIdx.x;   // 0..511 (column pair)
    const float2* col = (const float2*)(g_H + (size_t)t * BATCH * HDIM) + j2;

    float s0 = 0.f, s1 = 0.f, q0 = 0.f, q1 = 0.f;
#pragma unroll 8
    for (int b = 0; b < BATCH; b++) {
        const float2 v = col[b * (HDIM / 2)];
        s0 += v.x;  q0 += v.x * v.x;
        s1 += v.y;  q1 += v.y * v.y;
    }
    const float inv = 1.0f / (float)BATCH;
    const float m0 = s0 * inv, m1 = s1 * inv;
    const int j = j2 * 2;
    g_mean[t * HDIM + j]     = m0;
    g_mean[t * HDIM + j + 1] = m1;
    g_istd[t * HDIM + j]     = rsqrtf(q0 * inv - m0 * m0 + 1e-4f);
    g_istd[t * HDIM + j + 1] = rsqrtf(q1 * inv - m1 * m1 + 1e-4f);
}

// ============================================================================
// Kernel 3: LIF recurrence -> spike counts S[b,j]   (unchanged)
// ============================================================================
__global__ void recurrence_kernel(const float* __restrict__ gamma)
{
    const int idx = blockIdx.x * 256 + threadIdx.x;   // b*1024 + j
    const int j = idx & (HDIM - 1);

    float mem = 0.f;
    float cnt = 0.f;
#pragma unroll
    for (int t = 0; t < T_STEPS; t++) {
        const float h  = g_H[(size_t)t * (BATCH * HDIM) + idx];
        const float hn = gamma[t * HDIM + j] * (h - g_mean[t * HDIM + j]) *
                         g_istd[t * HDIM + j];
        mem = 0.95f * mem + hn;
        if (mem > 1.0f) { cnt += 1.0f; mem -= 1.0f; }
    }
    g_S[idx] = cnt;
}

// ============================================================================
// Kernel 4a: transpose W2 [100,1024] -> W2T [1024,128]   (unchanged)
// ============================================================================
__global__ void transposeW2_kernel(const float* __restrict__ W2)
{
    const int idx = blockIdx.x * 256 + threadIdx.x;   // 0..131071
    const int k = idx >> 7;
    const int c = idx & 127;
    g_W2T[idx] = (c < CDIM) ? W2[c * HDIM + k] : 0.0f;
}

// ============================================================================
// Kernel 4b: out[b,c] = (1/T) * sum_k S[b,k] * W2T[k,c]   (unchanged)
// ============================================================================
__global__ void out_gemm_kernel(float* __restrict__ out)
{
    __shared__ float sS[8][HDIM];
    const int bb  = blockIdx.x;       // 0..63
    const int tid = threadIdx.x;

    for (int i = tid; i < 8 * HDIM; i += 256) {
        const int r = i >> 10, c = i & (HDIM - 1);
        sS[r][c] = g_S[(bb * 8 + r) * HDIM + c];
    }
    __syncthreads();

    const int br = tid >> 5;   // 0..7
    const int cq = tid & 31;   // 0..31 (25 active -> 100 cols)

    float4 acc = make_float4(0.f, 0.f, 0.f, 0.f);
#pragma unroll 8
    for (int k = 0; k < HDIM; k++) {
        const float  s = sS[br][k];                                 // broadcast
        const float4 w = *(const float4*)&g_W2T[k * 128 + cq * 4];  // coalesced
        acc.x += s * w.x;  acc.y += s * w.y;
        acc.z += s * w.z;  acc.w += s * w.w;
    }
    if (cq < 25) {
        const float sc = 1.0f / (float)T_STEPS;
        float4 o = make_float4(acc.x * sc, acc.y * sc, acc.z * sc, acc.w * sc);
        *(float4*)&out[(bb * 8 + br) * CDIM + cq * 4] = o;
    }
}

// ============================================================================
// launch
// ============================================================================
extern "C" void kernel_launch(void* const* d_in, const int* in_sizes, int n_in,
                              void* d_out, int out_size)
{
    const float* z     = (const float*)d_in[0];   // [20,512,4096]
    const float* W1    = (const float*)d_in[1];   // [1024,4096]
    const float* gamma = (const float*)d_in[2];   // [20,1024]
    const float* W2    = (const float*)d_in[3];   // [100,1024]
    float* out = (float*)d_out;                   // [512,100]

    gemm1_kernel<<<dim3(8, 80, KSPLIT), 256>>>(z, W1);
    merge_kernel<<<(unsigned)(HELEMS / 4 / 256), 256>>>();
    bn_stats_kernel<<<dim3(4, 20), 128>>>();
    recurrence_kernel<<<(BATCH * HDIM) / 256, 256>>>(gamma);
    transposeW2_kernel<<<(HDIM * 128) / 256, 256>>>(W2);
    out_gemm_kernel<<<BATCH / 8, 256>>>(out);
}